// round 1
// baseline (speedup 1.0000x reference)
#include <cuda_runtime.h>
#include <math.h>

#define B_  16
#define N_  1024
#define C_  768
#define H_  12
#define HD_ 64
#define NC3 2304
#define MROWS (B_*N_)

// Scratch (allocation-free rule: __device__ globals)
__device__ float g_q[B_*H_*N_*HD_];
__device__ float g_k[B_*H_*N_*HD_];
__device__ float g_v[B_*H_*N_*HD_];
__device__ float g_o[B_*N_*C_];

// ---------------------------------------------------------------------------
// QKV GEMM: [16384,768] @ [768,2304] + bias, scatter epilogue into q/k/v
// in [B,H,N,hd] layout. 128x128x8 tiles, 256 threads, 8x8 microtile.
// ---------------------------------------------------------------------------
__global__ __launch_bounds__(256) void qkv_gemm(const float* __restrict__ X,
                                                const float* __restrict__ W,
                                                const float* __restrict__ bias) {
    __shared__ float As[8][128];
    __shared__ float Bs[8][128];
    const int tid = threadIdx.x;
    const int bc = blockIdx.x, br = blockIdx.y;
    const int K = C_, NC = NC3;

    const int arow = tid >> 1, ac4 = (tid & 1) * 4;
    const int brow = tid >> 5, bc4 = (tid & 31) * 4;
    const float* Ap = X + (size_t)(br * 128 + arow) * K + ac4;
    const float* Bp = W + (size_t)brow * NC + bc * 128 + bc4;

    float acc[8][8];
    #pragma unroll
    for (int i = 0; i < 8; i++)
        #pragma unroll
        for (int j = 0; j < 8; j++) acc[i][j] = 0.0f;

    const int ty = tid >> 4, tx = tid & 15;

    for (int k0 = 0; k0 < K; k0 += 8) {
        float4 a  = *(const float4*)(Ap + k0);
        float4 bb = *(const float4*)(Bp + (size_t)k0 * NC);
        As[ac4 + 0][arow] = a.x;
        As[ac4 + 1][arow] = a.y;
        As[ac4 + 2][arow] = a.z;
        As[ac4 + 3][arow] = a.w;
        *(float4*)(&Bs[brow][bc4]) = bb;
        __syncthreads();
        #pragma unroll
        for (int kk = 0; kk < 8; kk++) {
            float ar[8], brv[8];
            *(float4*)(ar)     = *(const float4*)(&As[kk][ty * 8]);
            *(float4*)(ar + 4) = *(const float4*)(&As[kk][ty * 8 + 4]);
            *(float4*)(brv)     = *(const float4*)(&Bs[kk][tx * 8]);
            *(float4*)(brv + 4) = *(const float4*)(&Bs[kk][tx * 8 + 4]);
            #pragma unroll
            for (int i = 0; i < 8; i++)
                #pragma unroll
                for (int j = 0; j < 8; j++)
                    acc[i][j] = fmaf(ar[i], brv[j], acc[i][j]);
        }
        __syncthreads();
    }

    // Scatter epilogue: col j -> (s, h, d) = (j/768, (j%768)/64, j%64)
    #pragma unroll
    for (int i = 0; i < 8; i++) {
        int grow = br * 128 + ty * 8 + i;
        int b = grow >> 10, n = grow & 1023;
        #pragma unroll
        for (int j = 0; j < 8; j++) {
            int gcol = bc * 128 + tx * 8 + j;
            float v = acc[i][j] + bias[gcol];
            int s = gcol / 768;
            int rem = gcol - s * 768;
            int h = rem >> 6, d = rem & 63;
            float* dst = (s == 0) ? g_q : ((s == 1) ? g_k : g_v);
            dst[((size_t)(b * H_ + h) * N_ + n) * HD_ + d] = v;
        }
    }
}

// ---------------------------------------------------------------------------
// RoPE on q and k, in place. One thread per element; partner d^16 via shfl.
// 32-dim blocks: d<32 uses pos_h, d>=32 uses pos_w.
// out[d] = t[d]*cos(p*inv[loc/2]) + rot[d]*sin(p*inv[loc/2]);
// rot[d] = (loc<16) ? -t[d+16] : t[d-16]
// ---------------------------------------------------------------------------
__global__ __launch_bounds__(256) void rope_kernel(const int* __restrict__ pos_h,
                                                   const int* __restrict__ pos_w) {
    const int total_rows = B_ * H_ * N_;
    int e = blockIdx.x * 256 + threadIdx.x;  // [0, 2*rows*64)
    int tensor = e / (total_rows * HD_);
    int er = e - tensor * total_rows * HD_;
    int row = er >> 6;       // (b*H + h)*N + n
    int d = er & 63;
    int b = row / (H_ * N_);
    int n = row & (N_ - 1);

    float* base = tensor == 0 ? g_q : g_k;
    float* p = base + (size_t)row * HD_;

    int half = d >> 5;       // 0: pos_h, 1: pos_w
    int loc = d & 31;
    int pos = half ? pos_w[b * N_ + n] : pos_h[b * N_ + n];

    float inv = powf(10000.0f, -(float)(2 * (loc >> 1)) / 32.0f);
    float ang = (float)pos * inv;
    float sn, cs;
    sincosf(ang, &sn, &cs);

    float t = p[d];
    float other = __shfl_xor_sync(0xffffffffu, t, 16);
    float rot = ((loc & 16) == 0) ? -other : other;
    p[d] = t * cs + rot * sn;
}

// ---------------------------------------------------------------------------
// Attention: grid (N/128, H, B), 128 threads; thread = 1 query row.
// Online softmax over 16-key tiles staged in smem (broadcast LDS).
// Writes directly into [B,N,C] layout for the proj GEMM.
// ---------------------------------------------------------------------------
__global__ __launch_bounds__(128) void attn_kernel() {
    const int b = blockIdx.z, h = blockIdx.y;
    const int n = blockIdx.x * 128 + threadIdx.x;
    const int tid = threadIdx.x;
    const float SCALE = 0.125f;  // 64^-0.5

    __shared__ float Ks[16][64];
    __shared__ float Vs[16][64];

    const size_t bh = (size_t)(b * H_ + h) * N_;
    const float* qp = g_q + (bh + n) * HD_;
    float q[64];
    #pragma unroll
    for (int d4 = 0; d4 < 16; d4++)
        *(float4*)(q + d4 * 4) = *(const float4*)(qp + d4 * 4);

    float m = -1e30f, l = 0.0f;
    float acc[64];
    #pragma unroll
    for (int d = 0; d < 64; d++) acc[d] = 0.0f;

    for (int kt = 0; kt < N_ / 16; kt++) {
        const float4* Kb = (const float4*)(g_k + (bh + kt * 16) * HD_);
        const float4* Vb = (const float4*)(g_v + (bh + kt * 16) * HD_);
        ((float4*)Ks)[tid * 2 + 0] = Kb[tid * 2 + 0];
        ((float4*)Ks)[tid * 2 + 1] = Kb[tid * 2 + 1];
        ((float4*)Vs)[tid * 2 + 0] = Vb[tid * 2 + 0];
        ((float4*)Vs)[tid * 2 + 1] = Vb[tid * 2 + 1];
        __syncthreads();

        float s[16];
        #pragma unroll
        for (int j = 0; j < 16; j++) {
            float sum = 0.0f;
            #pragma unroll
            for (int d4 = 0; d4 < 16; d4++) {
                float4 kk = *(const float4*)(&Ks[j][d4 * 4]);
                sum = fmaf(q[d4 * 4 + 0], kk.x, sum);
                sum = fmaf(q[d4 * 4 + 1], kk.y, sum);
                sum = fmaf(q[d4 * 4 + 2], kk.z, sum);
                sum = fmaf(q[d4 * 4 + 3], kk.w, sum);
            }
            s[j] = sum * SCALE;
        }

        float mn = m;
        #pragma unroll
        for (int j = 0; j < 16; j++) mn = fmaxf(mn, s[j]);
        float corr = __expf(m - mn);
        l *= corr;
        #pragma unroll
        for (int d = 0; d < 64; d++) acc[d] *= corr;

        #pragma unroll
        for (int j = 0; j < 16; j++) {
            float pj = __expf(s[j] - mn);
            l += pj;
            #pragma unroll
            for (int d4 = 0; d4 < 16; d4++) {
                float4 vv = *(const float4*)(&Vs[j][d4 * 4]);
                acc[d4 * 4 + 0] = fmaf(pj, vv.x, acc[d4 * 4 + 0]);
                acc[d4 * 4 + 1] = fmaf(pj, vv.y, acc[d4 * 4 + 1]);
                acc[d4 * 4 + 2] = fmaf(pj, vv.z, acc[d4 * 4 + 2]);
                acc[d4 * 4 + 3] = fmaf(pj, vv.w, acc[d4 * 4 + 3]);
            }
        }
        m = mn;
        __syncthreads();
    }

    float invl = 1.0f / l;
    float* op = g_o + ((size_t)(b * N_ + n)) * C_ + h * 64;
    #pragma unroll
    for (int d4 = 0; d4 < 16; d4++) {
        float4 o;
        o.x = acc[d4 * 4 + 0] * invl;
        o.y = acc[d4 * 4 + 1] * invl;
        o.z = acc[d4 * 4 + 2] * invl;
        o.w = acc[d4 * 4 + 3] * invl;
        *(float4*)(op + d4 * 4) = o;
    }
}

// ---------------------------------------------------------------------------
// Proj GEMM: g_o [16384,768] @ W_proj [768,768] + bias -> d_out
// ---------------------------------------------------------------------------
__global__ __launch_bounds__(256) void proj_gemm(const float* __restrict__ W,
                                                 const float* __restrict__ bias,
                                                 float* __restrict__ out) {
    __shared__ float As[8][128];
    __shared__ float Bs[8][128];
    const int tid = threadIdx.x;
    const int bc = blockIdx.x, br = blockIdx.y;
    const int K = C_, NC = C_;

    const int arow = tid >> 1, ac4 = (tid & 1) * 4;
    const int brow = tid >> 5, bc4 = (tid & 31) * 4;
    const float* Ap = g_o + (size_t)(br * 128 + arow) * K + ac4;
    const float* Bp = W + (size_t)brow * NC + bc * 128 + bc4;

    float acc[8][8];
    #pragma unroll
    for (int i = 0; i < 8; i++)
        #pragma unroll
        for (int j = 0; j < 8; j++) acc[i][j] = 0.0f;

    const int ty = tid >> 4, tx = tid & 15;

    for (int k0 = 0; k0 < K; k0 += 8) {
        float4 a  = *(const float4*)(Ap + k0);
        float4 bb = *(const float4*)(Bp + (size_t)k0 * NC);
        As[ac4 + 0][arow] = a.x;
        As[ac4 + 1][arow] = a.y;
        As[ac4 + 2][arow] = a.z;
        As[ac4 + 3][arow] = a.w;
        *(float4*)(&Bs[brow][bc4]) = bb;
        __syncthreads();
        #pragma unroll
        for (int kk = 0; kk < 8; kk++) {
            float ar[8], brv[8];
            *(float4*)(ar)     = *(const float4*)(&As[kk][ty * 8]);
            *(float4*)(ar + 4) = *(const float4*)(&As[kk][ty * 8 + 4]);
            *(float4*)(brv)     = *(const float4*)(&Bs[kk][tx * 8]);
            *(float4*)(brv + 4) = *(const float4*)(&Bs[kk][tx * 8 + 4]);
            #pragma unroll
            for (int i = 0; i < 8; i++)
                #pragma unroll
                for (int j = 0; j < 8; j++)
                    acc[i][j] = fmaf(ar[i], brv[j], acc[i][j]);
        }
        __syncthreads();
    }

    #pragma unroll
    for (int i = 0; i < 8; i++) {
        int grow = br * 128 + ty * 8 + i;
        float* orow = out + (size_t)grow * NC + bc * 128 + tx * 8;
        #pragma unroll
        for (int j = 0; j < 8; j++)
            orow[j] = acc[i][j] + bias[bc * 128 + tx * 8 + j];
    }
}

extern "C" void kernel_launch(void* const* d_in, const int* in_sizes, int n_in,
                              void* d_out, int out_size) {
    const float* x      = (const float*)d_in[0];
    const float* W_qkv  = (const float*)d_in[1];
    const float* b_qkv  = (const float*)d_in[2];
    const float* W_proj = (const float*)d_in[3];
    const float* b_proj = (const float*)d_in[4];
    const int*   pos_h  = (const int*)d_in[5];
    const int*   pos_w  = (const int*)d_in[6];
    float* out = (float*)d_out;

    qkv_gemm<<<dim3(NC3 / 128, MROWS / 128), 256>>>(x, W_qkv, b_qkv);

    int rope_elems = 2 * B_ * H_ * N_ * HD_;
    rope_kernel<<<rope_elems / 256, 256>>>(pos_h, pos_w);

    attn_kernel<<<dim3(N_ / 128, H_, B_), 128>>>();

    proj_gemm<<<dim3(C_ / 128, MROWS / 128), 256>>>(W_proj, b_proj, out);
}

// round 2
// speedup vs baseline: 2.1531x; 2.1531x over previous
#include <cuda_runtime.h>
#include <math.h>

#define B_  16
#define N_  1024
#define C_  768
#define H_  12
#define HD_ 64
#define NC3 2304
#define MROWS (B_*N_)

// Scratch (allocation-free rule: __device__ globals)
__device__ float g_q[B_*H_*N_*HD_];
__device__ float g_k[B_*H_*N_*HD_];
__device__ float g_v[B_*H_*N_*HD_];
__device__ float g_o[B_*N_*C_];

// ---------------------------------------------------------------------------
// tf32 helpers
// ---------------------------------------------------------------------------
__device__ __forceinline__ float tf32_rnd(float x) {
    unsigned r;
    asm("cvt.rna.tf32.f32 %0, %1;" : "=r"(r) : "f"(x));
    return __uint_as_float(r);
}

__device__ __forceinline__ void mma_tf32(float d[4], const unsigned a[4], const unsigned b[2]) {
    asm volatile(
        "mma.sync.aligned.m16n8k8.row.col.f32.tf32.tf32.f32 "
        "{%0,%1,%2,%3}, {%4,%5,%6,%7}, {%8,%9}, {%0,%1,%2,%3};"
        : "+f"(d[0]), "+f"(d[1]), "+f"(d[2]), "+f"(d[3])
        : "r"(a[0]), "r"(a[1]), "r"(a[2]), "r"(a[3]), "r"(b[0]), "r"(b[1]));
}

// ---------------------------------------------------------------------------
// Tensor-core GEMM, 3-term tf32 (near-fp32 accuracy).
// C[M,NC] = A[M,768] @ W[768,NC] + bias.
// MODE 0: A = param X, scatter epilogue into g_q/g_k/g_v ([B,H,N,hd]).
// MODE 1: A = g_o, plain epilogue into outp.
// 128x128x16 block tile, 256 threads (8 warps as 2x4), warp tile 64x32.
// ---------------------------------------------------------------------------
template<int NC, int MODE>
__global__ __launch_bounds__(256) void tc_gemm(const float* __restrict__ Xin,
                                               const float* __restrict__ Wt,
                                               const float* __restrict__ bias,
                                               float* __restrict__ outp) {
    __shared__ float Ah[16][136];
    __shared__ float Al[16][136];
    __shared__ float Bh[16][136];
    __shared__ float Bl[16][136];

    const int tid = threadIdx.x;
    const int lane = tid & 31, warp = tid >> 5;
    const int wm = (warp >> 2) * 64, wn = (warp & 3) * 32;
    const int row0 = blockIdx.y * 128, col0 = blockIdx.x * 128;

    const float* A = (MODE == 0) ? Xin : g_o;

    float acc[4][4][4];
    #pragma unroll
    for (int i = 0; i < 4; i++)
        #pragma unroll
        for (int j = 0; j < 4; j++)
            #pragma unroll
            for (int r = 0; r < 4; r++) acc[i][j][r] = 0.0f;

    const int am = tid >> 2;           // 0..63
    const int ak = (tid & 3) * 4;      // 0,4,8,12
    const int bk = tid >> 5;           // 0..7
    const int bn = (tid & 31) * 4;     // 0..124

    const int fr = lane >> 2, fc = lane & 3;

    for (int k0 = 0; k0 < C_; k0 += 16) {
        float4 a0 = *(const float4*)(A + (size_t)(row0 + am) * C_ + k0 + ak);
        float4 a1 = *(const float4*)(A + (size_t)(row0 + am + 64) * C_ + k0 + ak);
        float4 b0 = *(const float4*)(Wt + (size_t)(k0 + bk) * NC + col0 + bn);
        float4 b1 = *(const float4*)(Wt + (size_t)(k0 + bk + 8) * NC + col0 + bn);

        __syncthreads();   // previous iteration's fragment reads done

        {
            const float* va = (const float*)&a0;
            #pragma unroll
            for (int i = 0; i < 4; i++) {
                float h = tf32_rnd(va[i]);
                Ah[ak + i][am] = h;
                Al[ak + i][am] = tf32_rnd(va[i] - h);
            }
            const float* vb = (const float*)&a1;
            #pragma unroll
            for (int i = 0; i < 4; i++) {
                float h = tf32_rnd(vb[i]);
                Ah[ak + i][am + 64] = h;
                Al[ak + i][am + 64] = tf32_rnd(vb[i] - h);
            }
            float4 h4, l4;
            h4.x = tf32_rnd(b0.x); l4.x = tf32_rnd(b0.x - h4.x);
            h4.y = tf32_rnd(b0.y); l4.y = tf32_rnd(b0.y - h4.y);
            h4.z = tf32_rnd(b0.z); l4.z = tf32_rnd(b0.z - h4.z);
            h4.w = tf32_rnd(b0.w); l4.w = tf32_rnd(b0.w - h4.w);
            *(float4*)(&Bh[bk][bn]) = h4;
            *(float4*)(&Bl[bk][bn]) = l4;
            h4.x = tf32_rnd(b1.x); l4.x = tf32_rnd(b1.x - h4.x);
            h4.y = tf32_rnd(b1.y); l4.y = tf32_rnd(b1.y - h4.y);
            h4.z = tf32_rnd(b1.z); l4.z = tf32_rnd(b1.z - h4.z);
            h4.w = tf32_rnd(b1.w); l4.w = tf32_rnd(b1.w - h4.w);
            *(float4*)(&Bh[bk + 8][bn]) = h4;
            *(float4*)(&Bl[bk + 8][bn]) = l4;
        }
        __syncthreads();

        #pragma unroll
        for (int kk = 0; kk < 16; kk += 8) {
            unsigned ah[4][4], al[4][4], bh[4][2], bl[4][2];
            #pragma unroll
            for (int mt = 0; mt < 4; mt++) {
                int r = wm + mt * 16 + fr;
                ah[mt][0] = __float_as_uint(Ah[kk + fc][r]);
                ah[mt][1] = __float_as_uint(Ah[kk + fc][r + 8]);
                ah[mt][2] = __float_as_uint(Ah[kk + 4 + fc][r]);
                ah[mt][3] = __float_as_uint(Ah[kk + 4 + fc][r + 8]);
                al[mt][0] = __float_as_uint(Al[kk + fc][r]);
                al[mt][1] = __float_as_uint(Al[kk + fc][r + 8]);
                al[mt][2] = __float_as_uint(Al[kk + 4 + fc][r]);
                al[mt][3] = __float_as_uint(Al[kk + 4 + fc][r + 8]);
            }
            #pragma unroll
            for (int nt = 0; nt < 4; nt++) {
                int c = wn + nt * 8 + fr;
                bh[nt][0] = __float_as_uint(Bh[kk + fc][c]);
                bh[nt][1] = __float_as_uint(Bh[kk + 4 + fc][c]);
                bl[nt][0] = __float_as_uint(Bl[kk + fc][c]);
                bl[nt][1] = __float_as_uint(Bl[kk + 4 + fc][c]);
            }
            #pragma unroll
            for (int mt = 0; mt < 4; mt++)
                #pragma unroll
                for (int nt = 0; nt < 4; nt++) {
                    mma_tf32(acc[mt][nt], ah[mt], bh[nt]);
                    mma_tf32(acc[mt][nt], al[mt], bh[nt]);
                    mma_tf32(acc[mt][nt], ah[mt], bl[nt]);
                }
        }
    }

    // Epilogue. c0,c1 at (row, 2*fc .. +1); c2,c3 at (row+8, ...)
    #pragma unroll
    for (int mt = 0; mt < 4; mt++)
        #pragma unroll
        for (int nt = 0; nt < 4; nt++) {
            #pragma unroll
            for (int half = 0; half < 2; half++) {
                int gr = row0 + wm + mt * 16 + fr + half * 8;
                int gc = col0 + wn + nt * 8 + 2 * fc;
                float v0 = acc[mt][nt][half * 2 + 0] + bias[gc];
                float v1 = acc[mt][nt][half * 2 + 1] + bias[gc + 1];
                if (MODE == 0) {
                    int b = gr >> 10, n = gr & 1023;
                    int s = gc / 768;
                    int rem = gc - s * 768;
                    int h = rem >> 6, d = rem & 63;
                    float* dst = (s == 0) ? g_q : ((s == 1) ? g_k : g_v);
                    *(float2*)(dst + ((size_t)(b * H_ + h) * N_ + n) * HD_ + d) =
                        make_float2(v0, v1);
                } else {
                    *(float2*)(outp + (size_t)gr * NC + gc) = make_float2(v0, v1);
                }
            }
        }
}

// ---------------------------------------------------------------------------
// RoPE on q and k, in place. One thread per element; partner d^16 via shfl.
// ---------------------------------------------------------------------------
__global__ __launch_bounds__(256) void rope_kernel(const int* __restrict__ pos_h,
                                                   const int* __restrict__ pos_w) {
    const int total_rows = B_ * H_ * N_;
    int e = blockIdx.x * 256 + threadIdx.x;
    int tensor = e / (total_rows * HD_);
    int er = e - tensor * total_rows * HD_;
    int row = er >> 6;
    int d = er & 63;
    int b = row / (H_ * N_);
    int n = row & (N_ - 1);

    float* base = tensor == 0 ? g_q : g_k;
    float* p = base + (size_t)row * HD_;

    int half = d >> 5;
    int loc = d & 31;
    int pos = half ? pos_w[b * N_ + n] : pos_h[b * N_ + n];

    // 10000^(-2*(loc/2)/32) = 2^(-log2(1e4)/16 * (loc/2))
    float inv = exp2f(-0.83048202f * (float)(loc >> 1));
    float ang = (float)pos * inv;
    float sn, cs;
    sincosf(ang, &sn, &cs);

    float t = p[d];
    float other = __shfl_xor_sync(0xffffffffu, t, 16);
    float rot = ((loc & 16) == 0) ? -other : other;
    p[d] = t * cs + rot * sn;
}

// ---------------------------------------------------------------------------
// Attention: thread = 1 query row, online softmax, double-buffered 16-key
// K/V tiles (LDG->regs overlap compute, 1 sync/tile).
// ---------------------------------------------------------------------------
__global__ __launch_bounds__(128) void attn_kernel() {
    const int b = blockIdx.z, h = blockIdx.y;
    const int n = blockIdx.x * 128 + threadIdx.x;
    const int tid = threadIdx.x;
    const float SCALE = 0.125f;

    __shared__ float Ks[2][16][64];
    __shared__ float Vs[2][16][64];

    const size_t bh = (size_t)(b * H_ + h) * N_;
    const float* qp = g_q + (bh + n) * HD_;
    float q[64];
    #pragma unroll
    for (int d4 = 0; d4 < 16; d4++)
        *(float4*)(q + d4 * 4) = *(const float4*)(qp + d4 * 4);

    float m = -1e30f, l = 0.0f;
    float acc[64];
    #pragma unroll
    for (int d = 0; d < 64; d++) acc[d] = 0.0f;

    const float4* Kb = (const float4*)(g_k + bh * HD_);
    const float4* Vb = (const float4*)(g_v + bh * HD_);

    float4 kr0, kr1, vr0, vr1;
    // preload tile 0
    kr0 = Kb[tid * 2]; kr1 = Kb[tid * 2 + 1];
    vr0 = Vb[tid * 2]; vr1 = Vb[tid * 2 + 1];
    ((float4*)Ks[0])[tid * 2] = kr0; ((float4*)Ks[0])[tid * 2 + 1] = kr1;
    ((float4*)Vs[0])[tid * 2] = vr0; ((float4*)Vs[0])[tid * 2 + 1] = vr1;
    __syncthreads();

    const int NT = N_ / 16;
    for (int kt = 0; kt < NT; kt++) {
        int cur = kt & 1;
        if (kt + 1 < NT) {
            int off = (kt + 1) * 256 + tid * 2;
            kr0 = Kb[off]; kr1 = Kb[off + 1];
            vr0 = Vb[off]; vr1 = Vb[off + 1];
        }

        float s[16];
        #pragma unroll
        for (int j = 0; j < 16; j++) {
            float sum = 0.0f;
            #pragma unroll
            for (int d4 = 0; d4 < 16; d4++) {
                float4 kk = *(const float4*)(&Ks[cur][j][d4 * 4]);
                sum = fmaf(q[d4 * 4 + 0], kk.x, sum);
                sum = fmaf(q[d4 * 4 + 1], kk.y, sum);
                sum = fmaf(q[d4 * 4 + 2], kk.z, sum);
                sum = fmaf(q[d4 * 4 + 3], kk.w, sum);
            }
            s[j] = sum * SCALE;
        }

        float mn = m;
        #pragma unroll
        for (int j = 0; j < 16; j++) mn = fmaxf(mn, s[j]);
        float corr = __expf(m - mn);
        l *= corr;
        #pragma unroll
        for (int d = 0; d < 64; d++) acc[d] *= corr;

        #pragma unroll
        for (int j = 0; j < 16; j++) {
            float pj = __expf(s[j] - mn);
            l += pj;
            #pragma unroll
            for (int d4 = 0; d4 < 16; d4++) {
                float4 vv = *(const float4*)(&Vs[cur][j][d4 * 4]);
                acc[d4 * 4 + 0] = fmaf(pj, vv.x, acc[d4 * 4 + 0]);
                acc[d4 * 4 + 1] = fmaf(pj, vv.y, acc[d4 * 4 + 1]);
                acc[d4 * 4 + 2] = fmaf(pj, vv.z, acc[d4 * 4 + 2]);
                acc[d4 * 4 + 3] = fmaf(pj, vv.w, acc[d4 * 4 + 3]);
            }
        }
        m = mn;

        if (kt + 1 < NT) {
            int nxt = cur ^ 1;
            ((float4*)Ks[nxt])[tid * 2] = kr0; ((float4*)Ks[nxt])[tid * 2 + 1] = kr1;
            ((float4*)Vs[nxt])[tid * 2] = vr0; ((float4*)Vs[nxt])[tid * 2 + 1] = vr1;
        }
        __syncthreads();
    }

    float invl = 1.0f / l;
    float* op = g_o + ((size_t)(b * N_ + n)) * C_ + h * 64;
    #pragma unroll
    for (int d4 = 0; d4 < 16; d4++) {
        float4 o;
        o.x = acc[d4 * 4 + 0] * invl;
        o.y = acc[d4 * 4 + 1] * invl;
        o.z = acc[d4 * 4 + 2] * invl;
        o.w = acc[d4 * 4 + 3] * invl;
        *(float4*)(op + d4 * 4) = o;
    }
}

extern "C" void kernel_launch(void* const* d_in, const int* in_sizes, int n_in,
                              void* d_out, int out_size) {
    const float* x      = (const float*)d_in[0];
    const float* W_qkv  = (const float*)d_in[1];
    const float* b_qkv  = (const float*)d_in[2];
    const float* W_proj = (const float*)d_in[3];
    const float* b_proj = (const float*)d_in[4];
    const int*   pos_h  = (const int*)d_in[5];
    const int*   pos_w  = (const int*)d_in[6];
    float* out = (float*)d_out;

    tc_gemm<NC3, 0><<<dim3(NC3 / 128, MROWS / 128), 256>>>(x, W_qkv, b_qkv, nullptr);

    int rope_elems = 2 * B_ * H_ * N_ * HD_;
    rope_kernel<<<rope_elems / 256, 256>>>(pos_h, pos_w);

    attn_kernel<<<dim3(N_ / 128, H_, B_), 128>>>();

    tc_gemm<C_, 1><<<dim3(C_ / 128, MROWS / 128), 256>>>(nullptr, W_proj, b_proj, out);
}

// round 4
// speedup vs baseline: 2.6039x; 1.2094x over previous
#include <cuda_runtime.h>
#include <math.h>

#define B_  16
#define N_  1024
#define C_  768
#define H_  12
#define HD_ 64
#define NC3 2304
#define MROWS (B_*N_)

// Scratch (allocation-free rule: __device__ globals)
__device__ float g_q[B_*H_*N_*HD_];
__device__ float g_k[B_*H_*N_*HD_];
__device__ float g_v[B_*H_*N_*HD_];
__device__ float g_o[B_*N_*C_];

// ---------------------------------------------------------------------------
// tf32 helpers
// ---------------------------------------------------------------------------
__device__ __forceinline__ float tf32_rnd(float x) {
    unsigned r;
    asm("cvt.rna.tf32.f32 %0, %1;" : "=r"(r) : "f"(x));
    return __uint_as_float(r);
}

__device__ __forceinline__ void mma_tf32(float d[4], const unsigned a[4], const unsigned b[2]) {
    asm volatile(
        "mma.sync.aligned.m16n8k8.row.col.f32.tf32.tf32.f32 "
        "{%0,%1,%2,%3}, {%4,%5,%6,%7}, {%8,%9}, {%0,%1,%2,%3};"
        : "+f"(d[0]), "+f"(d[1]), "+f"(d[2]), "+f"(d[3])
        : "r"(a[0]), "r"(a[1]), "r"(a[2]), "r"(a[3]), "r"(b[0]), "r"(b[1]));
}

__device__ __forceinline__ void split4(float4 v, float4& h, float4& l) {
    h.x = tf32_rnd(v.x); l.x = tf32_rnd(v.x - h.x);
    h.y = tf32_rnd(v.y); l.y = tf32_rnd(v.y - h.y);
    h.z = tf32_rnd(v.z); l.z = tf32_rnd(v.z - h.z);
    h.w = tf32_rnd(v.w); l.w = tf32_rnd(v.w - h.w);
}

// ---------------------------------------------------------------------------
// Tensor-core GEMM, 3-term tf32 (near-fp32 accuracy).
// MODE 0: A = param X, scatter epilogue into g_q/g_k/g_v ([B,H,N,hd]).
// MODE 1: A = g_o, plain epilogue into outp.
// ---------------------------------------------------------------------------
template<int NC, int MODE>
__global__ __launch_bounds__(256) void tc_gemm(const float* __restrict__ Xin,
                                               const float* __restrict__ Wt,
                                               const float* __restrict__ bias,
                                               float* __restrict__ outp) {
    __shared__ float Ah[16][136];
    __shared__ float Al[16][136];
    __shared__ float Bh[16][136];
    __shared__ float Bl[16][136];

    const int tid = threadIdx.x;
    const int lane = tid & 31, warp = tid >> 5;
    const int wm = (warp >> 2) * 64, wn = (warp & 3) * 32;
    const int row0 = blockIdx.y * 128, col0 = blockIdx.x * 128;

    const float* A = (MODE == 0) ? Xin : g_o;

    float acc[4][4][4];
    #pragma unroll
    for (int i = 0; i < 4; i++)
        #pragma unroll
        for (int j = 0; j < 4; j++)
            #pragma unroll
            for (int r = 0; r < 4; r++) acc[i][j][r] = 0.0f;

    const int am = tid >> 2;
    const int ak = (tid & 3) * 4;
    const int bk = tid >> 5;
    const int bn = (tid & 31) * 4;
    const int fr = lane >> 2, fc = lane & 3;

    for (int k0 = 0; k0 < C_; k0 += 16) {
        float4 a0 = *(const float4*)(A + (size_t)(row0 + am) * C_ + k0 + ak);
        float4 a1 = *(const float4*)(A + (size_t)(row0 + am + 64) * C_ + k0 + ak);
        float4 b0 = *(const float4*)(Wt + (size_t)(k0 + bk) * NC + col0 + bn);
        float4 b1 = *(const float4*)(Wt + (size_t)(k0 + bk + 8) * NC + col0 + bn);

        __syncthreads();

        {
            const float* va = (const float*)&a0;
            #pragma unroll
            for (int i = 0; i < 4; i++) {
                float h = tf32_rnd(va[i]);
                Ah[ak + i][am] = h;
                Al[ak + i][am] = tf32_rnd(va[i] - h);
            }
            const float* vb = (const float*)&a1;
            #pragma unroll
            for (int i = 0; i < 4; i++) {
                float h = tf32_rnd(vb[i]);
                Ah[ak + i][am + 64] = h;
                Al[ak + i][am + 64] = tf32_rnd(vb[i] - h);
            }
            float4 h4, l4;
            split4(b0, h4, l4);
            *(float4*)(&Bh[bk][bn]) = h4;
            *(float4*)(&Bl[bk][bn]) = l4;
            split4(b1, h4, l4);
            *(float4*)(&Bh[bk + 8][bn]) = h4;
            *(float4*)(&Bl[bk + 8][bn]) = l4;
        }
        __syncthreads();

        #pragma unroll
        for (int kk = 0; kk < 16; kk += 8) {
            unsigned ah[4][4], al[4][4], bh[4][2], bl[4][2];
            #pragma unroll
            for (int mt = 0; mt < 4; mt++) {
                int r = wm + mt * 16 + fr;
                ah[mt][0] = __float_as_uint(Ah[kk + fc][r]);
                ah[mt][1] = __float_as_uint(Ah[kk + fc][r + 8]);
                ah[mt][2] = __float_as_uint(Ah[kk + 4 + fc][r]);
                ah[mt][3] = __float_as_uint(Ah[kk + 4 + fc][r + 8]);
                al[mt][0] = __float_as_uint(Al[kk + fc][r]);
                al[mt][1] = __float_as_uint(Al[kk + fc][r + 8]);
                al[mt][2] = __float_as_uint(Al[kk + 4 + fc][r]);
                al[mt][3] = __float_as_uint(Al[kk + 4 + fc][r + 8]);
            }
            #pragma unroll
            for (int nt = 0; nt < 4; nt++) {
                int c = wn + nt * 8 + fr;
                bh[nt][0] = __float_as_uint(Bh[kk + fc][c]);
                bh[nt][1] = __float_as_uint(Bh[kk + 4 + fc][c]);
                bl[nt][0] = __float_as_uint(Bl[kk + fc][c]);
                bl[nt][1] = __float_as_uint(Bl[kk + 4 + fc][c]);
            }
            #pragma unroll
            for (int mt = 0; mt < 4; mt++)
                #pragma unroll
                for (int nt = 0; nt < 4; nt++) {
                    mma_tf32(acc[mt][nt], ah[mt], bh[nt]);
                    mma_tf32(acc[mt][nt], al[mt], bh[nt]);
                    mma_tf32(acc[mt][nt], ah[mt], bl[nt]);
                }
        }
    }

    #pragma unroll
    for (int mt = 0; mt < 4; mt++)
        #pragma unroll
        for (int nt = 0; nt < 4; nt++) {
            #pragma unroll
            for (int half = 0; half < 2; half++) {
                int gr = row0 + wm + mt * 16 + fr + half * 8;
                int gc = col0 + wn + nt * 8 + 2 * fc;
                float v0 = acc[mt][nt][half * 2 + 0] + bias[gc];
                float v1 = acc[mt][nt][half * 2 + 1] + bias[gc + 1];
                if (MODE == 0) {
                    int b = gr >> 10, n = gr & 1023;
                    int s = gc / 768;
                    int rem = gc - s * 768;
                    int h = rem >> 6, d = rem & 63;
                    float* dst = (s == 0) ? g_q : ((s == 1) ? g_k : g_v);
                    *(float2*)(dst + ((size_t)(b * H_ + h) * N_ + n) * HD_ + d) =
                        make_float2(v0, v1);
                } else {
                    *(float2*)(outp + (size_t)gr * NC + gc) = make_float2(v0, v1);
                }
            }
        }
}

// ---------------------------------------------------------------------------
// RoPE on q and k, in place.
// ---------------------------------------------------------------------------
__global__ __launch_bounds__(256) void rope_kernel(const int* __restrict__ pos_h,
                                                   const int* __restrict__ pos_w) {
    const int total_rows = B_ * H_ * N_;
    int e = blockIdx.x * 256 + threadIdx.x;
    int tensor = e / (total_rows * HD_);
    int er = e - tensor * total_rows * HD_;
    int row = er >> 6;
    int d = er & 63;
    int b = row / (H_ * N_);
    int n = row & (N_ - 1);

    float* base = tensor == 0 ? g_q : g_k;
    float* p = base + (size_t)row * HD_;

    int half = d >> 5;
    int loc = d & 31;
    int pos = half ? pos_w[b * N_ + n] : pos_h[b * N_ + n];

    float inv = exp2f(-0.83048202f * (float)(loc >> 1));
    float ang = (float)pos * inv;
    float sn, cs;
    sincosf(ang, &sn, &cs);

    float t = p[d];
    float other = __shfl_xor_sync(0xffffffffu, t, 16);
    float rot = ((loc & 16) == 0) ? -other : other;
    p[d] = t * cs + rot * sn;
}

// ---------------------------------------------------------------------------
// Tensor-core flash attention. Block = 64 q-rows, 4 warps (16 rows/warp).
// Loops 16 key tiles of 64. 3-term tf32 for QK^T and P*V.
// K tile smem: XOR-swizzled hi/lo [64][64]; V tile smem: pad-72 hi/lo.
// ---------------------------------------------------------------------------
__global__ __launch_bounds__(128) void attn_tc() {
    extern __shared__ float sm[];
    float* Kh = sm;                    // 64*64
    float* Kl = sm + 4096;             // 64*64
    float* Vh = sm + 8192;             // 64*72
    float* Vl = sm + 8192 + 4608;      // 64*72   total 17408 floats = 69632 B

    const int b = blockIdx.z, h = blockIdx.y;
    const int tid = threadIdx.x;
    const int warp = tid >> 5, lane = tid & 31;
    const int fr = lane >> 2, fc = lane & 3;
    const size_t bh = (size_t)(b * H_ + h) * N_;
    const int q0 = blockIdx.x * 64 + warp * 16;
    const float SCALE = 0.125f;

    // Q fragments hi/lo in registers (split once)
    unsigned qh[8][4], ql[8][4];
    {
        const float* Qg = g_q + (bh + q0) * HD_;
        #pragma unroll
        for (int kk = 0; kk < 8; kk++)
            #pragma unroll
            for (int j = 0; j < 4; j++) {
                int r = fr + (j & 1) * 8;
                int c = kk * 8 + fc + (j >> 1) * 4;
                float v = Qg[r * HD_ + c];
                float hv = tf32_rnd(v);
                qh[kk][j] = __float_as_uint(hv);
                ql[kk][j] = __float_as_uint(tf32_rnd(v - hv));
            }
    }

    float o[8][4];
    #pragma unroll
    for (int nt = 0; nt < 8; nt++)
        #pragma unroll
        for (int j = 0; j < 4; j++) o[nt][j] = 0.0f;
    float m0 = -1e30f, m1 = -1e30f, l0 = 0.0f, l1 = 0.0f;

    const float* Kg = g_k + bh * HD_;
    const float* Vg = g_v + bh * HD_;

    const int r = tid >> 1, halfsel = tid & 1;
    float4* Kh4 = (float4*)Kh; float4* Kl4 = (float4*)Kl;
    float4* Vh4 = (float4*)Vh; float4* Vl4 = (float4*)Vl;

    for (int kt = 0; kt < 16; kt++) {
        __syncthreads();
        // Stage K/V tile, pre-split hi/lo
        {
            const float4* krow = (const float4*)(Kg + (size_t)(kt * 64 + r) * HD_) + halfsel * 8;
            const float4* vrow = (const float4*)(Vg + (size_t)(kt * 64 + r) * HD_) + halfsel * 8;
            #pragma unroll
            for (int i = 0; i < 8; i++) {
                int d4 = halfsel * 8 + i;
                float4 hh, ll;
                split4(krow[i], hh, ll);
                int kidx = r * 16 + (d4 ^ (r & 7));
                Kh4[kidx] = hh; Kl4[kidx] = ll;
                split4(vrow[i], hh, ll);
                int vidx = r * 18 + d4;
                Vh4[vidx] = hh; Vl4[vidx] = ll;
            }
        }
        __syncthreads();

        // S = Q K^T  (p = raw scores)
        float p[8][4];
        #pragma unroll
        for (int nt = 0; nt < 8; nt++)
            #pragma unroll
            for (int j = 0; j < 4; j++) p[nt][j] = 0.0f;

        #pragma unroll
        for (int kk = 0; kk < 8; kk++) {
            #pragma unroll
            for (int nt = 0; nt < 8; nt++) {
                int key = nt * 8 + fr;
                int i0 = key * 64 + (((2 * kk)     ^ fr) << 2) + fc;
                int i1 = key * 64 + (((2 * kk + 1) ^ fr) << 2) + fc;
                unsigned kb[2] = { __float_as_uint(Kh[i0]), __float_as_uint(Kh[i1]) };
                unsigned klo[2] = { __float_as_uint(Kl[i0]), __float_as_uint(Kl[i1]) };
                mma_tf32(p[nt], qh[kk], kb);
                mma_tf32(p[nt], ql[kk], kb);
                mma_tf32(p[nt], qh[kk], klo);
            }
        }

        // Online softmax (rows fr and fr+8)
        float mx0 = -1e30f, mx1 = -1e30f;
        #pragma unroll
        for (int nt = 0; nt < 8; nt++) {
            mx0 = fmaxf(mx0, fmaxf(p[nt][0], p[nt][1]));
            mx1 = fmaxf(mx1, fmaxf(p[nt][2], p[nt][3]));
        }
        mx0 *= SCALE; mx1 *= SCALE;
        mx0 = fmaxf(mx0, __shfl_xor_sync(0xffffffffu, mx0, 1));
        mx0 = fmaxf(mx0, __shfl_xor_sync(0xffffffffu, mx0, 2));
        mx1 = fmaxf(mx1, __shfl_xor_sync(0xffffffffu, mx1, 1));
        mx1 = fmaxf(mx1, __shfl_xor_sync(0xffffffffu, mx1, 2));
        float mn0 = fmaxf(m0, mx0), mn1 = fmaxf(m1, mx1);
        float c0 = __expf(m0 - mn0), c1 = __expf(m1 - mn1);
        m0 = mn0; m1 = mn1;
        l0 *= c0; l1 *= c1;
        #pragma unroll
        for (int nt = 0; nt < 8; nt++) {
            o[nt][0] *= c0; o[nt][1] *= c0;
            o[nt][2] *= c1; o[nt][3] *= c1;
        }
        #pragma unroll
        for (int nt = 0; nt < 8; nt++) {
            p[nt][0] = __expf(fmaf(p[nt][0], SCALE, -mn0)); l0 += p[nt][0];
            p[nt][1] = __expf(fmaf(p[nt][1], SCALE, -mn0)); l0 += p[nt][1];
            p[nt][2] = __expf(fmaf(p[nt][2], SCALE, -mn1)); l1 += p[nt][2];
            p[nt][3] = __expf(fmaf(p[nt][3], SCALE, -mn1)); l1 += p[nt][3];
        }

        // O += P V : redistribute P (C-layout -> A-layout) via shfl, split, mma
        const int grp = lane & ~3;
        const int s1 = grp + (fc >> 1);
        const int s2 = s1 + 2;
        #pragma unroll
        for (int kk2 = 0; kk2 < 8; kk2++) {
            float x0 = __shfl_sync(0xffffffffu, p[kk2][0], s1);
            float x1 = __shfl_sync(0xffffffffu, p[kk2][1], s1);
            float y0 = __shfl_sync(0xffffffffu, p[kk2][0], s2);
            float y1 = __shfl_sync(0xffffffffu, p[kk2][1], s2);
            float x2 = __shfl_sync(0xffffffffu, p[kk2][2], s1);
            float x3 = __shfl_sync(0xffffffffu, p[kk2][3], s1);
            float y2 = __shfl_sync(0xffffffffu, p[kk2][2], s2);
            float y3 = __shfl_sync(0xffffffffu, p[kk2][3], s2);
            float a0 = (fc & 1) ? x1 : x0;
            float a1 = (fc & 1) ? x3 : x2;
            float a2 = (fc & 1) ? y1 : y0;
            float a3 = (fc & 1) ? y3 : y2;
            unsigned pah[4], pal[4];
            {
                float hv;
                hv = tf32_rnd(a0); pah[0] = __float_as_uint(hv); pal[0] = __float_as_uint(tf32_rnd(a0 - hv));
                hv = tf32_rnd(a1); pah[1] = __float_as_uint(hv); pal[1] = __float_as_uint(tf32_rnd(a1 - hv));
                hv = tf32_rnd(a2); pah[2] = __float_as_uint(hv); pal[2] = __float_as_uint(tf32_rnd(a2 - hv));
                hv = tf32_rnd(a3); pah[3] = __float_as_uint(hv); pal[3] = __float_as_uint(tf32_rnd(a3 - hv));
            }
            #pragma unroll
            for (int nt = 0; nt < 8; nt++) {
                int i0 = (kk2 * 8 + fc) * 72 + nt * 8 + fr;
                int i1 = (kk2 * 8 + fc + 4) * 72 + nt * 8 + fr;
                unsigned vb[2]  = { __float_as_uint(Vh[i0]), __float_as_uint(Vh[i1]) };
                unsigned vlo[2] = { __float_as_uint(Vl[i0]), __float_as_uint(Vl[i1]) };
                mma_tf32(o[nt], pah, vb);
                mma_tf32(o[nt], pal, vb);
                mma_tf32(o[nt], pah, vlo);
            }
        }
    }

    // Final normalize + write to g_o [B,N,C]
    l0 += __shfl_xor_sync(0xffffffffu, l0, 1);
    l0 += __shfl_xor_sync(0xffffffffu, l0, 2);
    l1 += __shfl_xor_sync(0xffffffffu, l1, 1);
    l1 += __shfl_xor_sync(0xffffffffu, l1, 2);
    float il0 = 1.0f / l0, il1 = 1.0f / l1;

    float* orow0 = g_o + (size_t)(b * N_ + q0 + fr) * C_ + h * 64;
    float* orow1 = orow0 + 8 * C_;
    #pragma unroll
    for (int nt = 0; nt < 8; nt++) {
        *(float2*)(orow0 + nt * 8 + 2 * fc) = make_float2(o[nt][0] * il0, o[nt][1] * il0);
        *(float2*)(orow1 + nt * 8 + 2 * fc) = make_float2(o[nt][2] * il1, o[nt][3] * il1);
    }
}

extern "C" void kernel_launch(void* const* d_in, const int* in_sizes, int n_in,
                              void* d_out, int out_size) {
    const float* x      = (const float*)d_in[0];
    const float* W_qkv  = (const float*)d_in[1];
    const float* b_qkv  = (const float*)d_in[2];
    const float* W_proj = (const float*)d_in[3];
    const float* b_proj = (const float*)d_in[4];
    const int*   pos_h  = (const int*)d_in[5];
    const int*   pos_w  = (const int*)d_in[6];
    float* out = (float*)d_out;

    tc_gemm<NC3, 0><<<dim3(NC3 / 128, MROWS / 128), 256>>>(x, W_qkv, b_qkv, nullptr);

    int rope_elems = 2 * B_ * H_ * N_ * HD_;
    rope_kernel<<<rope_elems / 256, 256>>>(pos_h, pos_w);

    static int smem_set = 0;
    if (!smem_set) {
        cudaFuncSetAttribute(attn_tc, cudaFuncAttributeMaxDynamicSharedMemorySize, 69632);
        smem_set = 1;
    }
    attn_tc<<<dim3(N_ / 64, H_, B_), 128, 69632>>>();

    tc_gemm<C_, 1><<<dim3(C_ / 128, MROWS / 128), 256>>>(nullptr, W_proj, b_proj, out);
}

// round 8
// speedup vs baseline: 4.6195x; 1.7741x over previous
#include <cuda_runtime.h>
#include <cuda_bf16.h>
#include <math.h>

#define B_  16
#define N_  1024
#define C_  768
#define H_  12
#define HD_ 64
#define NC3 2304
#define MROWS (B_*N_)

// Scratch (allocation-free rule: __device__ globals)
__device__ float g_q[B_*H_*N_*HD_];
__device__ float g_k[B_*H_*N_*HD_];
__device__ float g_v[B_*H_*N_*HD_];
__device__ float g_o[B_*N_*C_];

// ---------------------------------------------------------------------------
// bf16 split helpers.  Pack (x,y) -> bf16x2 (x in low half = even k), plus
// bf16x2 of the residuals. hi/lo 2-term split: err ~2^-18 per product term.
// ---------------------------------------------------------------------------
__device__ __forceinline__ void bsplit2(float x, float y, unsigned& h, unsigned& l) {
    unsigned hb;
    asm("cvt.rn.bf16x2.f32 %0, %1, %2;" : "=r"(hb) : "f"(y), "f"(x));
    float hx = __uint_as_float(hb << 16);
    float hy = __uint_as_float(hb & 0xffff0000u);
    unsigned lb;
    asm("cvt.rn.bf16x2.f32 %0, %1, %2;" : "=r"(lb) : "f"(y - hy), "f"(x - hx));
    h = hb; l = lb;
}

__device__ __forceinline__ void mma_bf16(float d[4], const unsigned a[4], const unsigned b[2]) {
    asm volatile(
        "mma.sync.aligned.m16n8k16.row.col.f32.bf16.bf16.f32 "
        "{%0,%1,%2,%3}, {%4,%5,%6,%7}, {%8,%9}, {%0,%1,%2,%3};"
        : "+f"(d[0]), "+f"(d[1]), "+f"(d[2]), "+f"(d[3])
        : "r"(a[0]), "r"(a[1]), "r"(a[2]), "r"(a[3]), "r"(b[0]), "r"(b[1]));
}

// ---------------------------------------------------------------------------
// Tensor-core GEMM, 3-term bf16 (near-fp32 accuracy).
// C[M,NC] = A[M,768] @ W[768,NC] + bias.
// MODE 0: A = param X, scatter epilogue into g_q/g_k/g_v ([B,H,N,hd]).
// MODE 1: A = g_o, plain epilogue into outp.
// 128x128x32 tile, 256 threads (8 warps, 2x4), warp tile 64x32.
// Smem: pair-packed (2 bf16 along k per u32), layout [kpair][m] / [kpair][n],
// row stride 136 -> conflict-free fragment loads.
// ---------------------------------------------------------------------------
template<int NC, int MODE>
__global__ __launch_bounds__(256) void tc_gemm(const float* __restrict__ Xin,
                                               const float* __restrict__ Wt,
                                               const float* __restrict__ bias,
                                               float* __restrict__ outp) {
    __shared__ unsigned Ah_s[16 * 136];
    __shared__ unsigned Al_s[16 * 136];
    __shared__ unsigned Bh_s[16 * 136];
    __shared__ unsigned Bl_s[16 * 136];

    const int tid = threadIdx.x;
    const int lane = tid & 31, warp = tid >> 5;
    const int wm = (warp >> 2) * 64, wn = (warp & 3) * 32;
    const int row0 = blockIdx.y * 128, col0 = blockIdx.x * 128;
    const int fr = lane >> 2, fc = lane & 3;

    const float* A = (MODE == 0) ? Xin : g_o;

    float acc[4][4][4];
    #pragma unroll
    for (int i = 0; i < 4; i++)
        #pragma unroll
        for (int j = 0; j < 4; j++)
            #pragma unroll
            for (int r = 0; r < 4; r++) acc[i][j][r] = 0.0f;

    const int am = tid >> 1;            // 0..127
    const int aks = (tid & 1) * 16;     // k-seg within 32

    for (int k0 = 0; k0 < C_; k0 += 32) {
        // ---- global loads ----
        const float* Ap = A + (size_t)(row0 + am) * C_ + k0 + aks;
        float4 av[4];
        #pragma unroll
        for (int i = 0; i < 4; i++) av[i] = ((const float4*)Ap)[i];

        const float* B0 = Wt + (size_t)(k0 + 2 * warp) * NC + col0 + lane * 4;
        float4 r0 = *(const float4*)B0;
        float4 r1 = *(const float4*)(B0 + NC);
        float4 r2 = *(const float4*)(B0 + 16 * (size_t)NC);
        float4 r3 = *(const float4*)(B0 + 17 * (size_t)NC);

        __syncthreads();   // previous iteration's fragment reads done

        // ---- stage A (pairs along k, layout [kpair][m]) ----
        #pragma unroll
        for (int i = 0; i < 4; i++) {
            unsigned h, l;
            bsplit2(av[i].x, av[i].y, h, l);
            Ah_s[(aks / 2 + 2 * i) * 136 + am] = h;
            Al_s[(aks / 2 + 2 * i) * 136 + am] = l;
            bsplit2(av[i].z, av[i].w, h, l);
            Ah_s[(aks / 2 + 2 * i + 1) * 136 + am] = h;
            Al_s[(aks / 2 + 2 * i + 1) * 136 + am] = l;
        }
        // ---- stage B (pairs along k, layout [kpair][n], STS.128) ----
        {
            unsigned h[4], l[4];
            bsplit2(r0.x, r1.x, h[0], l[0]);
            bsplit2(r0.y, r1.y, h[1], l[1]);
            bsplit2(r0.z, r1.z, h[2], l[2]);
            bsplit2(r0.w, r1.w, h[3], l[3]);
            *(uint4*)&Bh_s[warp * 136 + lane * 4] = make_uint4(h[0], h[1], h[2], h[3]);
            *(uint4*)&Bl_s[warp * 136 + lane * 4] = make_uint4(l[0], l[1], l[2], l[3]);
            bsplit2(r2.x, r3.x, h[0], l[0]);
            bsplit2(r2.y, r3.y, h[1], l[1]);
            bsplit2(r2.z, r3.z, h[2], l[2]);
            bsplit2(r2.w, r3.w, h[3], l[3]);
            *(uint4*)&Bh_s[(warp + 8) * 136 + lane * 4] = make_uint4(h[0], h[1], h[2], h[3]);
            *(uint4*)&Bl_s[(warp + 8) * 136 + lane * 4] = make_uint4(l[0], l[1], l[2], l[3]);
        }
        __syncthreads();

        // ---- mma ----
        #pragma unroll
        for (int kk = 0; kk < 2; kk++) {
            const int p0 = (kk * 8 + fc) * 136, p1 = (kk * 8 + fc + 4) * 136;
            unsigned ah[4][4], al[4][4], bh[4][2], bl[4][2];
            #pragma unroll
            for (int mt = 0; mt < 4; mt++) {
                int r = wm + mt * 16 + fr;
                ah[mt][0] = Ah_s[p0 + r];     ah[mt][1] = Ah_s[p0 + r + 8];
                ah[mt][2] = Ah_s[p1 + r];     ah[mt][3] = Ah_s[p1 + r + 8];
                al[mt][0] = Al_s[p0 + r];     al[mt][1] = Al_s[p0 + r + 8];
                al[mt][2] = Al_s[p1 + r];     al[mt][3] = Al_s[p1 + r + 8];
            }
            #pragma unroll
            for (int nt = 0; nt < 4; nt++) {
                int c = wn + nt * 8 + fr;
                bh[nt][0] = Bh_s[p0 + c];     bh[nt][1] = Bh_s[p1 + c];
                bl[nt][0] = Bl_s[p0 + c];     bl[nt][1] = Bl_s[p1 + c];
            }
            #pragma unroll
            for (int mt = 0; mt < 4; mt++)
                #pragma unroll
                for (int nt = 0; nt < 4; nt++) {
                    mma_bf16(acc[mt][nt], ah[mt], bh[nt]);
                    mma_bf16(acc[mt][nt], al[mt], bh[nt]);
                    mma_bf16(acc[mt][nt], ah[mt], bl[nt]);
                }
        }
    }

    // ---- epilogue ----
    #pragma unroll
    for (int mt = 0; mt < 4; mt++)
        #pragma unroll
        for (int nt = 0; nt < 4; nt++) {
            #pragma unroll
            for (int half = 0; half < 2; half++) {
                int gr = row0 + wm + mt * 16 + fr + half * 8;
                int gc = col0 + wn + nt * 8 + 2 * fc;
                float v0 = acc[mt][nt][half * 2 + 0] + bias[gc];
                float v1 = acc[mt][nt][half * 2 + 1] + bias[gc + 1];
                if (MODE == 0) {
                    int b = gr >> 10, n = gr & 1023;
                    int s = gc / 768;
                    int rem = gc - s * 768;
                    int h = rem >> 6, d = rem & 63;
                    float* dst = (s == 0) ? g_q : ((s == 1) ? g_k : g_v);
                    *(float2*)(dst + ((size_t)(b * H_ + h) * N_ + n) * HD_ + d) =
                        make_float2(v0, v1);
                } else {
                    *(float2*)(outp + (size_t)gr * NC + gc) = make_float2(v0, v1);
                }
            }
        }
}

// ---------------------------------------------------------------------------
// RoPE on q and k, in place.
// ---------------------------------------------------------------------------
__global__ __launch_bounds__(256) void rope_kernel(const int* __restrict__ pos_h,
                                                   const int* __restrict__ pos_w) {
    const int total_rows = B_ * H_ * N_;
    int e = blockIdx.x * 256 + threadIdx.x;
    int tensor = e / (total_rows * HD_);
    int er = e - tensor * total_rows * HD_;
    int row = er >> 6;
    int d = er & 63;
    int b = row / (H_ * N_);
    int n = row & (N_ - 1);

    float* base = tensor == 0 ? g_q : g_k;
    float* p = base + (size_t)row * HD_;

    int half = d >> 5;
    int loc = d & 31;
    int pos = half ? pos_w[b * N_ + n] : pos_h[b * N_ + n];

    float inv = exp2f(-0.83048202f * (float)(loc >> 1));
    float ang = (float)pos * inv;
    float sn, cs;
    sincosf(ang, &sn, &cs);

    float t = p[d];
    float other = __shfl_xor_sync(0xffffffffu, t, 16);
    float rot = ((loc & 16) == 0) ? -other : other;
    p[d] = t * cs + rot * sn;
}

// ---------------------------------------------------------------------------
// bf16 tensor-core flash attention. Block = 64 q-rows, 4 warps (16 rows/warp),
// 16 key tiles of 64. 3-term bf16 splits for QK^T and P*V.
// K smem: pairs along d, layout [key][dpair], stride 36 (conflict-free).
// V smem: pairs along key, layout [d][keypair], stride 36 (conflict-free).
// S C-fragments feed P*V A-fragments directly (no shuffles).
// ---------------------------------------------------------------------------
__global__ __launch_bounds__(128) void attn_tc() {
    __shared__ unsigned Kh[64 * 36], Kl[64 * 36];
    __shared__ unsigned Vh[64 * 36], Vl[64 * 36];

    const int b = blockIdx.z, h = blockIdx.y;
    const int tid = threadIdx.x;
    const int warp = tid >> 5, lane = tid & 31;
    const int fr = lane >> 2, fc = lane & 3;
    const size_t bh = (size_t)(b * H_ + h) * N_;
    const int q0 = blockIdx.x * 64 + warp * 16;
    const float SCALE = 0.125f;

    // Q fragments hi/lo (split once)
    unsigned qh[4][4], ql[4][4];
    {
        const float* Qg = g_q + (bh + q0) * HD_;
        #pragma unroll
        for (int kk = 0; kk < 4; kk++)
            #pragma unroll
            for (int j = 0; j < 4; j++) {
                int r = fr + (j & 1) * 8;
                int c = kk * 16 + (j >> 1) * 8 + 2 * fc;
                bsplit2(Qg[r * HD_ + c], Qg[r * HD_ + c + 1], qh[kk][j], ql[kk][j]);
            }
    }

    float o[8][4];
    #pragma unroll
    for (int nt = 0; nt < 8; nt++)
        #pragma unroll
        for (int j = 0; j < 4; j++) o[nt][j] = 0.0f;
    float m0 = -1e30f, m1 = -1e30f, l0 = 0.0f, l1 = 0.0f;

    const float* Kg = g_k + bh * HD_;
    const float* Vg = g_v + bh * HD_;

    for (int kt = 0; kt < 16; kt++) {
        __syncthreads();
        // ---- stage K: thread -> (key = tid/2, half-row of 32 d) ----
        {
            int key = tid >> 1, ds = (tid & 1) * 32;
            const float4* krow = (const float4*)(Kg + (size_t)(kt * 64 + key) * HD_ + ds);
            unsigned hp[16], lp[16];
            #pragma unroll
            for (int i = 0; i < 8; i++) {
                float4 v = krow[i];
                bsplit2(v.x, v.y, hp[2 * i], lp[2 * i]);
                bsplit2(v.z, v.w, hp[2 * i + 1], lp[2 * i + 1]);
            }
            int base = key * 36 + ds / 2;
            #pragma unroll
            for (int u = 0; u < 4; u++) {
                *(uint4*)&Kh[base + 4 * u] = make_uint4(hp[4*u], hp[4*u+1], hp[4*u+2], hp[4*u+3]);
                *(uint4*)&Kl[base + 4 * u] = make_uint4(lp[4*u], lp[4*u+1], lp[4*u+2], lp[4*u+3]);
            }
        }
        // ---- stage V: pairs along key, layout [d][keypair] ----
        {
            int kp = tid >> 2;
            const float* v0p = Vg + (size_t)(kt * 64 + 2 * kp) * HD_;
            const float* v1p = v0p + HD_;
            #pragma unroll
            for (int i = 0; i < 4; i++) {
                int d4 = (tid & 3) * 4 + 16 * i;
                float4 a = *(const float4*)(v0p + d4);
                float4 c = *(const float4*)(v1p + d4);
                unsigned hh, ll;
                bsplit2(a.x, c.x, hh, ll); Vh[(d4+0)*36 + kp] = hh; Vl[(d4+0)*36 + kp] = ll;
                bsplit2(a.y, c.y, hh, ll); Vh[(d4+1)*36 + kp] = hh; Vl[(d4+1)*36 + kp] = ll;
                bsplit2(a.z, c.z, hh, ll); Vh[(d4+2)*36 + kp] = hh; Vl[(d4+2)*36 + kp] = ll;
                bsplit2(a.w, c.w, hh, ll); Vh[(d4+3)*36 + kp] = hh; Vl[(d4+3)*36 + kp] = ll;
            }
        }
        __syncthreads();

        // ---- S = Q K^T ----
        float p[8][4];
        #pragma unroll
        for (int nt = 0; nt < 8; nt++)
            #pragma unroll
            for (int j = 0; j < 4; j++) p[nt][j] = 0.0f;

        #pragma unroll
        for (int kk = 0; kk < 4; kk++) {
            #pragma unroll
            for (int nt = 0; nt < 8; nt++) {
                int key = nt * 8 + fr;
                int i0 = key * 36 + kk * 8 + fc;
                unsigned kb[2]  = { Kh[i0], Kh[i0 + 4] };
                unsigned klo[2] = { Kl[i0], Kl[i0 + 4] };
                mma_bf16(p[nt], qh[kk], kb);
                mma_bf16(p[nt], ql[kk], kb);
                mma_bf16(p[nt], qh[kk], klo);
            }
        }

        // ---- online softmax (rows fr and fr+8) ----
        float mx0 = -1e30f, mx1 = -1e30f;
        #pragma unroll
        for (int nt = 0; nt < 8; nt++) {
            mx0 = fmaxf(mx0, fmaxf(p[nt][0], p[nt][1]));
            mx1 = fmaxf(mx1, fmaxf(p[nt][2], p[nt][3]));
        }
        mx0 *= SCALE; mx1 *= SCALE;
        mx0 = fmaxf(mx0, __shfl_xor_sync(0xffffffffu, mx0, 1));
        mx0 = fmaxf(mx0, __shfl_xor_sync(0xffffffffu, mx0, 2));
        mx1 = fmaxf(mx1, __shfl_xor_sync(0xffffffffu, mx1, 1));
        mx1 = fmaxf(mx1, __shfl_xor_sync(0xffffffffu, mx1, 2));
        float mn0 = fmaxf(m0, mx0), mn1 = fmaxf(m1, mx1);
        float c0 = __expf(m0 - mn0), c1 = __expf(m1 - mn1);
        m0 = mn0; m1 = mn1;
        l0 *= c0; l1 *= c1;
        #pragma unroll
        for (int nt = 0; nt < 8; nt++) {
            o[nt][0] *= c0; o[nt][1] *= c0;
            o[nt][2] *= c1; o[nt][3] *= c1;
        }
        #pragma unroll
        for (int nt = 0; nt < 8; nt++) {
            p[nt][0] = __expf(fmaf(p[nt][0], SCALE, -mn0)); l0 += p[nt][0];
            p[nt][1] = __expf(fmaf(p[nt][1], SCALE, -mn0)); l0 += p[nt][1];
            p[nt][2] = __expf(fmaf(p[nt][2], SCALE, -mn1)); l1 += p[nt][2];
            p[nt][3] = __expf(fmaf(p[nt][3], SCALE, -mn1)); l1 += p[nt][3];
        }

        // ---- O += P V : C-fragment feeds A-fragment directly ----
        #pragma unroll
        for (int kk2 = 0; kk2 < 4; kk2++) {
            unsigned pah[4], pal[4];
            bsplit2(p[2*kk2][0],   p[2*kk2][1],   pah[0], pal[0]);
            bsplit2(p[2*kk2][2],   p[2*kk2][3],   pah[1], pal[1]);
            bsplit2(p[2*kk2+1][0], p[2*kk2+1][1], pah[2], pal[2]);
            bsplit2(p[2*kk2+1][2], p[2*kk2+1][3], pah[3], pal[3]);
            #pragma unroll
            for (int nt = 0; nt < 8; nt++) {
                int d = nt * 8 + fr;
                int i0 = d * 36 + kk2 * 8 + fc;
                unsigned vb[2]  = { Vh[i0], Vh[i0 + 4] };
                unsigned vlo[2] = { Vl[i0], Vl[i0 + 4] };
                mma_bf16(o[nt], pah, vb);
                mma_bf16(o[nt], pal, vb);
                mma_bf16(o[nt], pah, vlo);
            }
        }
    }

    // ---- finalize ----
    l0 += __shfl_xor_sync(0xffffffffu, l0, 1);
    l0 += __shfl_xor_sync(0xffffffffu, l0, 2);
    l1 += __shfl_xor_sync(0xffffffffu, l1, 1);
    l1 += __shfl_xor_sync(0xffffffffu, l1, 2);
    float il0 = 1.0f / l0, il1 = 1.0f / l1;

    float* orow0 = g_o + (size_t)(b * N_ + q0 + fr) * C_ + h * 64;
    float* orow1 = orow0 + 8 * C_;
    #pragma unroll
    for (int nt = 0; nt < 8; nt++) {
        *(float2*)(orow0 + nt * 8 + 2 * fc) = make_float2(o[nt][0] * il0, o[nt][1] * il0);
        *(float2*)(orow1 + nt * 8 + 2 * fc) = make_float2(o[nt][2] * il1, o[nt][3] * il1);
    }
}

extern "C" void kernel_launch(void* const* d_in, const int* in_sizes, int n_in,
                              void* d_out, int out_size) {
    const float* x      = (const float*)d_in[0];
    const float* W_qkv  = (const float*)d_in[1];
    const float* b_qkv  = (const float*)d_in[2];
    const float* W_proj = (const float*)d_in[3];
    const float* b_proj = (const float*)d_in[4];
    const int*   pos_h  = (const int*)d_in[5];
    const int*   pos_w  = (const int*)d_in[6];
    float* out = (float*)d_out;

    tc_gemm<NC3, 0><<<dim3(NC3 / 128, MROWS / 128), 256>>>(x, W_qkv, b_qkv, nullptr);

    int rope_elems = 2 * B_ * H_ * N_ * HD_;
    rope_kernel<<<rope_elems / 256, 256>>>(pos_h, pos_w);

    attn_tc<<<dim3(N_ / 64, H_, B_), 128>>>();

    tc_gemm<C_, 1><<<dim3(C_ / 128, MROWS / 128), 256>>>(nullptr, W_proj, b_proj, out);
}